// round 4
// baseline (speedup 1.0000x reference)
#include <cuda_runtime.h>
#include <cuda_bf16.h>

#define N_NODES 50000
#define E_EDGES 1600000
#define E_TOT   (E_EDGES + N_NODES)
#define C       128

// ---------------- scratch (device globals; no allocation allowed) ----------
__device__ float g_h[N_NODES * C];     // 25.6 MB  h = x @ W
__device__ float g_as[N_NODES];        // alpha_src per node
__device__ float g_ad[N_NODES];        // alpha_dst per node
__device__ float g_denom[N_NODES];     // softmax denominator per dst
__device__ float g_ex[E_TOT];          // exp(leaky(e)) per edge

// ---------------- init: zero d_out and denom -------------------------------
__global__ void k_init(float4* __restrict__ out) {
    int i = blockIdx.x * blockDim.x + threadIdx.x;
    int stride = gridDim.x * blockDim.x;
    const float4 z = make_float4(0.f, 0.f, 0.f, 0.f);
    for (int j = i; j < N_NODES * C / 4; j += stride) out[j] = z;
    for (int j = i; j < N_NODES; j += stride) g_denom[j] = 0.f;
}

// ---------------- fused GEMM + attention dots ------------------------------
// Block: 256 threads, computes 64 rows of h (64 x 128). K=128 split in two
// 64-wide chunks so static smem stays at exactly 48 KB.
// Warp w owns rows 8w..8w+7; lane l owns cols 4l..4l+3 (float4).
__global__ __launch_bounds__(256) void k_gemm(
    const float* __restrict__ x, const float* __restrict__ W,
    const float* __restrict__ a_src, const float* __restrict__ a_dst)
{
    __shared__ float Ws[64][128];   // 32 KB: W chunk [k 64][col 128]
    __shared__ float xs[64][64];    // 16 KB: x tile  [row 64][k 64]

    const int tid  = threadIdx.x;
    const int lane = tid & 31;
    const int warp = tid >> 5;
    const int rowBase = blockIdx.x * 64;

    float acc[8][4];
#pragma unroll
    for (int r = 0; r < 8; r++)
#pragma unroll
        for (int c = 0; c < 4; c++) acc[r][c] = 0.f;

    for (int kc = 0; kc < 2; kc++) {
        // W chunk: rows kc*64..+63, 128 cols = 2048 float4 / 256 threads
        const float4* Wg  = (const float4*)(W + kc * 64 * C);
        float4*       Wsv = (float4*)&Ws[0][0];
#pragma unroll
        for (int i = 0; i < 8; i++) Wsv[tid + 256 * i] = Wg[tid + 256 * i];
        // x tile: 64 rows x 64 k = 1024 float4 / 256 threads
#pragma unroll
        for (int i = 0; i < 4; i++) {
            int idx = tid + 256 * i;      // 0..1023
            int r   = idx >> 4;           // row in tile
            int f   = idx & 15;           // float4 within 64-col chunk
            int grow = rowBase + r;
            float4 v = make_float4(0.f, 0.f, 0.f, 0.f);
            if (grow < N_NODES)
                v = *(const float4*)(x + (size_t)grow * C + kc * 64 + f * 4);
            ((float4*)&xs[r][0])[f] = v;
        }
        __syncthreads();
#pragma unroll
        for (int kk = 0; kk < 64; kk++) {
            float4 wv = *(const float4*)&Ws[kk][lane * 4];
#pragma unroll
            for (int r = 0; r < 8; r++) {
                float xv = xs[warp * 8 + r][kk];       // warp broadcast
                acc[r][0] = fmaf(xv, wv.x, acc[r][0]);
                acc[r][1] = fmaf(xv, wv.y, acc[r][1]);
                acc[r][2] = fmaf(xv, wv.z, acc[r][2]);
                acc[r][3] = fmaf(xv, wv.w, acc[r][3]);
            }
        }
        __syncthreads();
    }

    // epilogue: store h, and reduce alpha_s / alpha_d dots across the warp
    const float4 av = *(const float4*)(a_src + lane * 4);
    const float4 bv = *(const float4*)(a_dst + lane * 4);
#pragma unroll
    for (int r = 0; r < 8; r++) {
        int grow = rowBase + warp * 8 + r;
        float s = acc[r][0]*av.x + acc[r][1]*av.y + acc[r][2]*av.z + acc[r][3]*av.w;
        float d = acc[r][0]*bv.x + acc[r][1]*bv.y + acc[r][2]*bv.z + acc[r][3]*bv.w;
#pragma unroll
        for (int off = 16; off; off >>= 1) {
            s += __shfl_xor_sync(0xffffffffu, s, off);
            d += __shfl_xor_sync(0xffffffffu, d, off);
        }
        if (grow < N_NODES) {
            *(float4*)(g_h + (size_t)grow * C + lane * 4) =
                make_float4(acc[r][0], acc[r][1], acc[r][2], acc[r][3]);
            if (lane == 0) { g_as[grow] = s; g_ad[grow] = d; }
        }
    }
}

// ---------------- edge pass: exp(leaky(e)) + denominator -------------------
// Segment-max is skipped (mathematically invariant; |e| <~ 9 so no overflow,
// and the 1e-16 eps is <=1e-16 relative once the max term is in the sum).
__global__ void k_edge(const int* __restrict__ ei) {
    int i = blockIdx.x * blockDim.x + threadIdx.x;
    int stride = gridDim.x * blockDim.x;
    for (int e = i; e < E_TOT; e += stride) {
        int s, d;
        if (e < E_EDGES) { s = __ldg(ei + e); d = __ldg(ei + E_EDGES + e); }
        else             { s = e - E_EDGES;   d = s; }
        float v = __ldg(g_as + s) + __ldg(g_ad + d);
        v = v > 0.f ? v : 0.2f * v;                 // leaky_relu(0.2)
        float ex = __expf(v);
        g_ex[e] = ex;
        atomicAdd(&g_denom[d], ex);
    }
}

// ---------------- aggregation: out[dst] += h[src] * alpha ------------------
// One warp per edge; lane l handles cols 4l..4l+3. Scatter via vector
// reduction (red.global.add.v4.f32) — 4x fewer L2 atomic ops than scalar.
__global__ __launch_bounds__(256) void k_agg(const int* __restrict__ ei,
                                             float* __restrict__ out) {
    const int lane = threadIdx.x & 31;
    int gw = (blockIdx.x * blockDim.x + threadIdx.x) >> 5;
    int nw = (gridDim.x * blockDim.x) >> 5;
    for (int e = gw; e < E_TOT; e += nw) {
        int s, d;
        if (e < E_EDGES) { s = __ldg(ei + e); d = __ldg(ei + E_EDGES + e); }
        else             { s = e - E_EDGES;   d = s; }
        float alpha = __ldg(g_ex + e) / __ldg(g_denom + d);
        float4 hv = *(const float4*)(g_h + (size_t)s * C + lane * 4);
        float4 v  = make_float4(hv.x * alpha, hv.y * alpha,
                                hv.z * alpha, hv.w * alpha);
        float* p = out + (size_t)d * C + lane * 4;
        asm volatile("red.global.add.v4.f32 [%0], {%1, %2, %3, %4};"
                     :: "l"(p), "f"(v.x), "f"(v.y), "f"(v.z), "f"(v.w)
                     : "memory");
    }
}

// ---------------- epilogue: out = relu(out + bias) -------------------------
__global__ void k_final(float4* __restrict__ out, const float* __restrict__ bias) {
    int i = blockIdx.x * blockDim.x + threadIdx.x;
    int stride = gridDim.x * blockDim.x;
    for (int j = i; j < N_NODES * C / 4; j += stride) {
        float4 v = out[j];
        const float4 b = *(const float4*)(bias + (j & 31) * 4);  // C/4 = 32
        v.x = fmaxf(v.x + b.x, 0.f);
        v.y = fmaxf(v.y + b.y, 0.f);
        v.z = fmaxf(v.z + b.z, 0.f);
        v.w = fmaxf(v.w + b.w, 0.f);
        out[j] = v;
    }
}

// ---------------- launch ---------------------------------------------------
extern "C" void kernel_launch(void* const* d_in, const int* in_sizes, int n_in,
                              void* d_out, int out_size) {
    const float* x     = (const float*)d_in[0];
    const float* W     = (const float*)d_in[1];
    const float* a_src = (const float*)d_in[2];
    const float* a_dst = (const float*)d_in[3];
    const float* bias  = (const float*)d_in[4];
    const int*   ei    = (const int*)d_in[5];
    float* out = (float*)d_out;

    k_init<<<512, 256>>>((float4*)out);
    k_gemm<<<(N_NODES + 63) / 64, 256>>>(x, W, a_src, a_dst);
    k_edge<<<2048, 256>>>(ei);
    k_agg<<<4096, 256>>>(ei, out);
    k_final<<<512, 256>>>((float4*)out, bias);
}

// round 5
// speedup vs baseline: 1.3481x; 1.3481x over previous
#include <cuda_runtime.h>
#include <cuda_bf16.h>

#define N_NODES 50000
#define E_EDGES 1600000
#define E_TOT   (E_EDGES + N_NODES)
#define C       128

// ---------------- scratch (device globals) ---------------------------------
__device__ float g_h[N_NODES * C];       // 25.6 MB  h = x @ W
__device__ float g_as[N_NODES];          // alpha_src per node
__device__ float g_ad[N_NODES];          // alpha_dst per node
__device__ int   g_cnt[N_NODES];         // degree histogram
__device__ int   g_rowstart[N_NODES + 1];
__device__ int   g_cursor[N_NODES];
__device__ int   g_csr_src[E_TOT];       // 6.6 MB: src node per CSR slot

// ---------------- zero histogram -------------------------------------------
__global__ void k_zero() {
    int i = blockIdx.x * blockDim.x + threadIdx.x;
    if (i < N_NODES) g_cnt[i] = 0;
}

// ---------------- fused GEMM + attention dots (unchanged, works well) ------
__global__ __launch_bounds__(256) void k_gemm(
    const float* __restrict__ x, const float* __restrict__ W,
    const float* __restrict__ a_src, const float* __restrict__ a_dst)
{
    __shared__ float Ws[64][128];   // 32 KB
    __shared__ float xs[64][64];    // 16 KB

    const int tid  = threadIdx.x;
    const int lane = tid & 31;
    const int warp = tid >> 5;
    const int rowBase = blockIdx.x * 64;

    float acc[8][4];
#pragma unroll
    for (int r = 0; r < 8; r++)
#pragma unroll
        for (int c = 0; c < 4; c++) acc[r][c] = 0.f;

    for (int kc = 0; kc < 2; kc++) {
        const float4* Wg  = (const float4*)(W + kc * 64 * C);
        float4*       Wsv = (float4*)&Ws[0][0];
#pragma unroll
        for (int i = 0; i < 8; i++) Wsv[tid + 256 * i] = Wg[tid + 256 * i];
#pragma unroll
        for (int i = 0; i < 4; i++) {
            int idx = tid + 256 * i;
            int r   = idx >> 4;
            int f   = idx & 15;
            int grow = rowBase + r;
            float4 v = make_float4(0.f, 0.f, 0.f, 0.f);
            if (grow < N_NODES)
                v = *(const float4*)(x + (size_t)grow * C + kc * 64 + f * 4);
            ((float4*)&xs[r][0])[f] = v;
        }
        __syncthreads();
#pragma unroll
        for (int kk = 0; kk < 64; kk++) {
            float4 wv = *(const float4*)&Ws[kk][lane * 4];
#pragma unroll
            for (int r = 0; r < 8; r++) {
                float xv = xs[warp * 8 + r][kk];
                acc[r][0] = fmaf(xv, wv.x, acc[r][0]);
                acc[r][1] = fmaf(xv, wv.y, acc[r][1]);
                acc[r][2] = fmaf(xv, wv.z, acc[r][2]);
                acc[r][3] = fmaf(xv, wv.w, acc[r][3]);
            }
        }
        __syncthreads();
    }

    const float4 av = *(const float4*)(a_src + lane * 4);
    const float4 bv = *(const float4*)(a_dst + lane * 4);
#pragma unroll
    for (int r = 0; r < 8; r++) {
        int grow = rowBase + warp * 8 + r;
        float s = acc[r][0]*av.x + acc[r][1]*av.y + acc[r][2]*av.z + acc[r][3]*av.w;
        float d = acc[r][0]*bv.x + acc[r][1]*bv.y + acc[r][2]*bv.z + acc[r][3]*bv.w;
#pragma unroll
        for (int off = 16; off; off >>= 1) {
            s += __shfl_xor_sync(0xffffffffu, s, off);
            d += __shfl_xor_sync(0xffffffffu, d, off);
        }
        if (grow < N_NODES) {
            *(float4*)(g_h + (size_t)grow * C + lane * 4) =
                make_float4(acc[r][0], acc[r][1], acc[r][2], acc[r][3]);
            if (lane == 0) { g_as[grow] = s; g_ad[grow] = d; }
        }
    }
}

// ---------------- CSR build: histogram -------------------------------------
__global__ void k_count(const int* __restrict__ ei) {
    int i = blockIdx.x * blockDim.x + threadIdx.x;
    int stride = gridDim.x * blockDim.x;
    for (int e = i; e < E_TOT; e += stride) {
        int d = (e < E_EDGES) ? __ldg(ei + E_EDGES + e) : (e - E_EDGES);
        atomicAdd(&g_cnt[d], 1);
    }
}

// ---------------- CSR build: single-block exclusive scan -------------------
__global__ void k_scan() {
    __shared__ int warp_sums[32];
    __shared__ int s_carry;
    const int tid = threadIdx.x, lane = tid & 31, wid = tid >> 5;
    if (tid == 0) s_carry = 0;
    __syncthreads();

    for (int base = 0; base < N_NODES; base += 1024) {
        int i = base + tid;
        int v = (i < N_NODES) ? g_cnt[i] : 0;
        // warp-inclusive scan
        int x = v;
#pragma unroll
        for (int off = 1; off < 32; off <<= 1) {
            int y = __shfl_up_sync(0xffffffffu, x, off);
            if (lane >= off) x += y;
        }
        if (lane == 31) warp_sums[wid] = x;
        __syncthreads();
        if (wid == 0) {
            int w = warp_sums[lane];
            int xw = w;
#pragma unroll
            for (int off = 1; off < 32; off <<= 1) {
                int y = __shfl_up_sync(0xffffffffu, xw, off);
                if (lane >= off) xw += y;
            }
            warp_sums[lane] = xw - w;   // exclusive warp offsets
        }
        __syncthreads();
        int excl = x - v + warp_sums[wid] + s_carry;
        if (i < N_NODES) { g_rowstart[i] = excl; g_cursor[i] = excl; }
        __syncthreads();                 // all reads of s_carry done
        if (tid == 1023) s_carry = excl + v;   // block-inclusive total
        __syncthreads();
    }
    if (threadIdx.x == 0) g_rowstart[N_NODES] = s_carry;  // == E_TOT
}

// ---------------- CSR build: scatter ---------------------------------------
__global__ void k_scatter(const int* __restrict__ ei) {
    int i = blockIdx.x * blockDim.x + threadIdx.x;
    int stride = gridDim.x * blockDim.x;
    for (int e = i; e < E_TOT; e += stride) {
        int s, d;
        if (e < E_EDGES) { s = __ldg(ei + e); d = __ldg(ei + E_EDGES + e); }
        else             { s = e - E_EDGES;   d = s; }
        int pos = atomicAdd(&g_cursor[d], 1);
        g_csr_src[pos] = s;
    }
}

// ---------------- fused softmax + aggregation + bias + relu ----------------
// Warp-per-dst. Unnormalized form: out = relu((Σ ex·h[src]) / (Σ ex + eps) + b)
// so no separate denom pass, no edge-weight storage, no output atomics.
__global__ __launch_bounds__(256) void k_agg(float* __restrict__ out,
                                             const float* __restrict__ bias) {
    const int lane = threadIdx.x & 31;
    const int d = (blockIdx.x * blockDim.x + threadIdx.x) >> 5;
    if (d >= N_NODES) return;

    const int rs = g_rowstart[d];
    const int re = g_rowstart[d + 1];
    const float add = __ldg(g_ad + d);

    float4 acc = make_float4(0.f, 0.f, 0.f, 0.f);
    float den = 0.f;

    for (int base = rs; base < re; base += 32) {
        int j = base + lane;
        int s = 0; float ex = 0.f;
        if (j < re) {
            s = __ldg(g_csr_src + j);
            float e = __ldg(g_as + s) + add;
            e = e > 0.f ? e : 0.2f * e;
            ex = __expf(e);
            den += ex;
        }
        int m = re - base;
        if (m >= 32) {
#pragma unroll 8
            for (int k = 0; k < 32; k++) {
                int   ss = __shfl_sync(0xffffffffu, s, k);
                float ee = __shfl_sync(0xffffffffu, ex, k);
                const float4 hv = *(const float4*)(g_h + (size_t)ss * C + lane * 4);
                acc.x = fmaf(ee, hv.x, acc.x);
                acc.y = fmaf(ee, hv.y, acc.y);
                acc.z = fmaf(ee, hv.z, acc.z);
                acc.w = fmaf(ee, hv.w, acc.w);
            }
        } else {
            for (int k = 0; k < m; k++) {
                int   ss = __shfl_sync(0xffffffffu, s, k);
                float ee = __shfl_sync(0xffffffffu, ex, k);
                const float4 hv = *(const float4*)(g_h + (size_t)ss * C + lane * 4);
                acc.x = fmaf(ee, hv.x, acc.x);
                acc.y = fmaf(ee, hv.y, acc.y);
                acc.z = fmaf(ee, hv.z, acc.z);
                acc.w = fmaf(ee, hv.w, acc.w);
            }
        }
    }

#pragma unroll
    for (int off = 16; off; off >>= 1)
        den += __shfl_xor_sync(0xffffffffu, den, off);
    const float inv = 1.f / (den + 1e-16f);

    const float4 b = *(const float4*)(bias + lane * 4);
    float4 v;
    v.x = fmaxf(fmaf(acc.x, inv, b.x), 0.f);
    v.y = fmaxf(fmaf(acc.y, inv, b.y), 0.f);
    v.z = fmaxf(fmaf(acc.z, inv, b.z), 0.f);
    v.w = fmaxf(fmaf(acc.w, inv, b.w), 0.f);
    *(float4*)(out + (size_t)d * C + lane * 4) = v;
}

// ---------------- launch ---------------------------------------------------
extern "C" void kernel_launch(void* const* d_in, const int* in_sizes, int n_in,
                              void* d_out, int out_size) {
    const float* x     = (const float*)d_in[0];
    const float* W     = (const float*)d_in[1];
    const float* a_src = (const float*)d_in[2];
    const float* a_dst = (const float*)d_in[3];
    const float* bias  = (const float*)d_in[4];
    const int*   ei    = (const int*)d_in[5];
    float* out = (float*)d_out;

    k_zero<<<(N_NODES + 255) / 256, 256>>>();
    k_gemm<<<(N_NODES + 63) / 64, 256>>>(x, W, a_src, a_dst);
    k_count<<<2048, 256>>>(ei);
    k_scan<<<1, 1024>>>();
    k_scatter<<<2048, 256>>>(ei);
    k_agg<<<(N_NODES * 32 + 255) / 256, 256>>>(out, bias);
}